// round 4
// baseline (speedup 1.0000x reference)
#include <cuda_runtime.h>
#include <cuda_fp16.h>
#include <cstdint>
#include <math.h>

#define BD 8192
#define CD 2048
#define STRIDE_H 56          // halves per feature row (48 used + 8 pad)
#define STRIDE_B 112         // bytes per feature row

// Feature rows, fp16 hi/lo split, K=48 layout:
//   A rows: [hi(16) | hi(16) | lo(16)]   B rows: [hi(16) | lo(16) | hi(16)]
// so dot48 = hi.hi + hi.lo + lo.hi  (drops only lo.lo ~ 2^-22).
__device__ __align__(16) __half gA[2 * BD * STRIDE_H];
__device__ __align__(16) __half gB[2 * CD * STRIDE_H];

__device__ __forceinline__ uint32_t smem_u32(const void* p) {
    uint32_t a;
    asm("{ .reg .u64 t; cvta.to.shared.u64 t, %1; cvt.u32.u64 %0, t; }" : "=r"(a) : "l"(p));
    return a;
}

// ---------------- Kernel 1: feature precompute ----------------
__global__ void qk_pre(const float* __restrict__ x, const float* __restrict__ c,
                       int B, int C) {
    int t = blockIdx.x * blockDim.x + threadIdx.x;
    if (t >= B + C) return;
    bool isB = t >= B;
    int row = isB ? t - B : t;
    const float* src = (isB ? c : x) + row * 8;

    float cv[8], sv[8];
    #pragma unroll
    for (int j = 0; j < 8; j++) sincosf(0.5f * src[j], &sv[j], &cv[j]);

    float pf[4][4];
    #pragma unroll
    for (int p = 0; p < 4; p++) {
        pf[p][0] = cv[2*p] * cv[2*p+1];
        pf[p][1] = cv[2*p] * sv[2*p+1];
        pf[p][2] = sv[2*p] * cv[2*p+1];
        pf[p][3] = sv[2*p] * sv[2*p+1];
    }

    #pragma unroll
    for (int g = 0; g < 2; g++) {
        __align__(16) __half rowv[STRIDE_H];
        #pragma unroll
        for (int a = 0; a < 4; a++) {
            #pragma unroll
            for (int b = 0; b < 4; b++) {
                float f = pf[2*g][a] * pf[2*g+1][b];
                __half hi = __float2half_rn(f);
                __half lo = __float2half_rn(f - __half2float(hi));
                int i = a * 4 + b;
                rowv[i]      = hi;
                rowv[16 + i] = isB ? lo : hi;
                rowv[32 + i] = isB ? hi : lo;
            }
        }
        #pragma unroll
        for (int i = 48; i < STRIDE_H; i++) rowv[i] = __float2half_rn(0.f);

        __half* dst = (isB ? gB : gA) + ((size_t)g * (isB ? CD : BD) + row) * STRIDE_H;
        #pragma unroll
        for (int j = 0; j < 7; j++)
            ((uint4*)dst)[j] = ((const uint4*)rowv)[j];
    }
}

// ---------------- Kernel 2: HMMA tile kernel ----------------
// Block 128x128, 8 warps. Warp tile 32 rows x 64 cols.
// Smem: A0 | A1 | B0 | B1, each 128 rows x 112B = 14336B. Total 57344B.
#define SM_A0 0
#define SM_A1 14336
#define SM_B0 28672
#define SM_B1 43008
#define SM_TOTAL 57344

__device__ __forceinline__ void ldm_x4(uint32_t* r, uint32_t addr) {
    asm volatile("ldmatrix.sync.aligned.m8n8.x4.shared.b16 {%0,%1,%2,%3}, [%4];"
                 : "=r"(r[0]), "=r"(r[1]), "=r"(r[2]), "=r"(r[3]) : "r"(addr));
}
__device__ __forceinline__ void ldm_x2(uint32_t& r0, uint32_t& r1, uint32_t addr) {
    asm volatile("ldmatrix.sync.aligned.m8n8.x2.shared.b16 {%0,%1}, [%2];"
                 : "=r"(r0), "=r"(r1) : "r"(addr));
}
__device__ __forceinline__ void mma16816(float* d, const uint32_t* a,
                                         uint32_t b0, uint32_t b1) {
    asm volatile(
        "mma.sync.aligned.m16n8k16.row.col.f32.f16.f16.f32 "
        "{%0,%1,%2,%3}, {%4,%5,%6,%7}, {%8,%9}, {%0,%1,%2,%3};"
        : "+f"(d[0]), "+f"(d[1]), "+f"(d[2]), "+f"(d[3])
        : "r"(a[0]), "r"(a[1]), "r"(a[2]), "r"(a[3]), "r"(b0), "r"(b1));
}

__global__ void __launch_bounds__(256, 2)
qk_hmma(float* __restrict__ out, int C) {
    extern __shared__ __align__(16) unsigned char sm[];
    const int tid = threadIdx.x, wid = tid >> 5, lane = tid & 31;
    const int row0 = blockIdx.y * 128, col0 = blockIdx.x * 128;

    // Tile copies (linear 16B chunks; 896 uint4 per tile).
    {
        const uint4* s0 = (const uint4*)(gA + (size_t)row0 * STRIDE_H);
        const uint4* s1 = (const uint4*)(gA + (size_t)(BD + row0) * STRIDE_H);
        const uint4* s2 = (const uint4*)(gB + (size_t)col0 * STRIDE_H);
        const uint4* s3 = (const uint4*)(gB + (size_t)(CD + col0) * STRIDE_H);
        uint4* d0 = (uint4*)(sm + SM_A0);
        uint4* d1 = (uint4*)(sm + SM_A1);
        uint4* d2 = (uint4*)(sm + SM_B0);
        uint4* d3 = (uint4*)(sm + SM_B1);
        for (int i = tid; i < 896; i += 256) {
            d0[i] = s0[i]; d1[i] = s1[i]; d2[i] = s2[i]; d3[i] = s3[i];
        }
    }
    __syncthreads();

    const int wr = wid & 3;        // row group: 32 rows
    const int wc = wid >> 2;       // col group: 64 cols
    const uint32_t sb = smem_u32(sm);

    // A fragment addresses: lanes 0-15 -> rows, lanes 16-31 -> +16B (cols 8-15).
    const uint32_t aoff = (uint32_t)(wr * 32 + (lane & 15)) * STRIDE_B + (lane >> 4) * 16;
    const uint32_t aAddr0 = sb + SM_A0 + aoff;
    const uint32_t aAddr1 = sb + SM_A1 + aoff;

    // Persistent a-fragments: [g][mt][kt][4]
    uint32_t af[2][2][3][4];
    #pragma unroll
    for (int mt = 0; mt < 2; mt++)
        #pragma unroll
        for (int kt = 0; kt < 3; kt++) {
            ldm_x4(af[0][mt][kt], aAddr0 + mt * 16 * STRIDE_B + kt * 32);
            ldm_x4(af[1][mt][kt], aAddr1 + mt * 16 * STRIDE_B + kt * 32);
        }

    // B fragment addresses: lanes 0-7 -> n rows k0, lanes 8-15 -> n rows +16B.
    const uint32_t boff = (uint32_t)(wc * 64 + (lane & 7)) * STRIDE_B + ((lane >> 3) & 1) * 16;
    const uint32_t bAddr0 = sb + SM_B0 + boff;
    const uint32_t bAddr1 = sb + SM_B1 + boff;

    const int colb = col0 + wc * 64 + (lane & 3) * 2;
    const size_t rbase = (size_t)(row0 + wr * 32 + (lane >> 2));

    #pragma unroll
    for (int nt = 0; nt < 8; nt++) {
        float acc1[2][4] = {{0.f,0.f,0.f,0.f},{0.f,0.f,0.f,0.f}};
        float acc2[2][4] = {{0.f,0.f,0.f,0.f},{0.f,0.f,0.f,0.f}};

        #pragma unroll
        for (int kt = 0; kt < 3; kt++) {
            uint32_t b0, b1;
            ldm_x2(b0, b1, bAddr0 + nt * 8 * STRIDE_B + kt * 32);
            mma16816(acc1[0], af[0][0][kt], b0, b1);
            mma16816(acc1[1], af[0][1][kt], b0, b1);
        }
        #pragma unroll
        for (int kt = 0; kt < 3; kt++) {
            uint32_t b0, b1;
            ldm_x2(b0, b1, bAddr1 + nt * 8 * STRIDE_B + kt * 32);
            mma16816(acc2[0], af[1][0][kt], b0, b1);
            mma16816(acc2[1], af[1][1][kt], b0, b1);
        }

        #pragma unroll
        for (int mt = 0; mt < 2; mt++) {
            size_t rm = rbase + mt * 16;
            float2 v;
            v.x = fabsf(acc1[mt][0] * acc2[mt][0]);
            v.y = fabsf(acc1[mt][1] * acc2[mt][1]);
            *(float2*)(out + rm * C + colb + nt * 8) = v;
            v.x = fabsf(acc1[mt][2] * acc2[mt][2]);
            v.y = fabsf(acc1[mt][3] * acc2[mt][3]);
            *(float2*)(out + (rm + 8) * C + colb + nt * 8) = v;
        }
    }
}

extern "C" void kernel_launch(void* const* d_in, const int* in_sizes, int n_in,
                              void* d_out, int out_size) {
    const float* x = (const float*)d_in[0];
    const float* c = (const float*)d_in[1];
    float* out = (float*)d_out;

    int B = in_sizes[0] / 8;   // 8192
    int C = in_sizes[1] / 8;   // 2048
    if (B > BD) B = BD;
    if (C > CD) C = CD;

    cudaFuncSetAttribute(qk_hmma, cudaFuncAttributeMaxDynamicSharedMemorySize, SM_TOTAL);

    int total = B + C;
    qk_pre<<<(total + 127) / 128, 128>>>(x, c, B, C);

    dim3 grid(C / 128, B / 128);
    qk_hmma<<<grid, 256, SM_TOTAL>>>(out, C);
}

// round 5
// speedup vs baseline: 1.2670x; 1.2670x over previous
#include <cuda_runtime.h>
#include <cuda_fp16.h>
#include <cstdint>
#include <math.h>

#define BD 8192
#define CD 2048
#define STRIDE_H 40          // halves per feature row (32 used + 8 pad)
#define STRIDE_B 80          // bytes per feature row (80r mod 128: conflict-free)

// Feature rows, fp16 hi/lo split, K=32 storage: [hi(16) | lo(16) | pad(8)].
// dot is computed as 3 MMA k-steps with operand combos:
//   ah.bh + ah.bl + al.bh   (drops only al.bl ~ 2^-22)
__device__ __align__(16) __half gA[2 * BD * STRIDE_H];
__device__ __align__(16) __half gB[2 * CD * STRIDE_H];

__device__ __forceinline__ uint32_t smem_u32(const void* p) {
    uint32_t a;
    asm("{ .reg .u64 t; cvta.to.shared.u64 t, %1; cvt.u32.u64 %0, t; }" : "=r"(a) : "l"(p));
    return a;
}

// ---------------- Kernel 1: feature precompute ----------------
__global__ void qk_pre(const float* __restrict__ x, const float* __restrict__ c,
                       int B, int C) {
    int t = blockIdx.x * blockDim.x + threadIdx.x;
    if (t >= B + C) return;
    bool isB = t >= B;
    int row = isB ? t - B : t;
    const float* src = (isB ? c : x) + row * 8;

    float cv[8], sv[8];
    #pragma unroll
    for (int j = 0; j < 8; j++) sincosf(0.5f * src[j], &sv[j], &cv[j]);

    float pf[4][4];
    #pragma unroll
    for (int p = 0; p < 4; p++) {
        pf[p][0] = cv[2*p] * cv[2*p+1];
        pf[p][1] = cv[2*p] * sv[2*p+1];
        pf[p][2] = sv[2*p] * cv[2*p+1];
        pf[p][3] = sv[2*p] * sv[2*p+1];
    }

    #pragma unroll
    for (int g = 0; g < 2; g++) {
        __align__(16) __half rowv[STRIDE_H];
        #pragma unroll
        for (int a = 0; a < 4; a++) {
            #pragma unroll
            for (int b = 0; b < 4; b++) {
                float f = pf[2*g][a] * pf[2*g+1][b];
                __half hi = __float2half_rn(f);
                __half lo = __float2half_rn(f - __half2float(hi));
                int i = a * 4 + b;
                rowv[i]      = hi;
                rowv[16 + i] = lo;
            }
        }
        #pragma unroll
        for (int i = 32; i < STRIDE_H; i++) rowv[i] = __float2half_rn(0.f);

        __half* dst = (isB ? gB : gA) + ((size_t)g * (isB ? CD : BD) + row) * STRIDE_H;
        #pragma unroll
        for (int j = 0; j < 5; j++)
            ((uint4*)dst)[j] = ((const uint4*)rowv)[j];
    }
}

// ---------------- Kernel 2: HMMA tile kernel ----------------
// Block 128x128, 8 warps, warp tile 32 rows x 64 cols, 3 CTAs/SM.
// Smem: A0 | A1 | B0 | B1, each 128 rows x 80B = 10240B. Total 40960B.
#define SM_A0 0
#define SM_A1 10240
#define SM_B0 20480
#define SM_B1 30720
#define SM_U4 2560           // total uint4 per CTA (per-array: 640)

__device__ __forceinline__ void ldm_x4(uint32_t* r, uint32_t addr) {
    asm volatile("ldmatrix.sync.aligned.m8n8.x4.shared.b16 {%0,%1,%2,%3}, [%4];"
                 : "=r"(r[0]), "=r"(r[1]), "=r"(r[2]), "=r"(r[3]) : "r"(addr));
}
__device__ __forceinline__ void mma16816(float* d, const uint32_t* a,
                                         uint32_t b0, uint32_t b1) {
    asm volatile(
        "mma.sync.aligned.m16n8k16.row.col.f32.f16.f16.f32 "
        "{%0,%1,%2,%3}, {%4,%5,%6,%7}, {%8,%9}, {%0,%1,%2,%3};"
        : "+f"(d[0]), "+f"(d[1]), "+f"(d[2]), "+f"(d[3])
        : "r"(a[0]), "r"(a[1]), "r"(a[2]), "r"(a[3]), "r"(b0), "r"(b1));
}

__global__ void __launch_bounds__(256, 3)
qk_hmma(float* __restrict__ out, int C) {
    __shared__ __align__(16) unsigned char sm[40960];
    const int tid = threadIdx.x, wid = tid >> 5, lane = tid & 31;
    const int row0 = blockIdx.y * 128, col0 = blockIdx.x * 128;

    // Tile copies: 640 uint4 per array, linear.
    {
        const uint4* s0 = (const uint4*)(gA + (size_t)row0 * STRIDE_H);
        const uint4* s1 = (const uint4*)(gA + (size_t)(BD + row0) * STRIDE_H);
        const uint4* s2 = (const uint4*)(gB + (size_t)col0 * STRIDE_H);
        const uint4* s3 = (const uint4*)(gB + (size_t)(CD + col0) * STRIDE_H);
        uint4* d0 = (uint4*)(sm + SM_A0);
        uint4* d1 = (uint4*)(sm + SM_A1);
        uint4* d2 = (uint4*)(sm + SM_B0);
        uint4* d3 = (uint4*)(sm + SM_B1);
        #pragma unroll
        for (int i = tid; i < 640; i += 256) {
            d0[i] = s0[i]; d1[i] = s1[i]; d2[i] = s2[i]; d3[i] = s3[i];
        }
    }
    __syncthreads();

    const int wr = wid & 3;        // row group: 32 rows
    const int wc = wid >> 2;       // col group: 64 cols
    const uint32_t sb = smem_u32(sm);

    // A fragments: lanes 0-15 -> rows, lanes 16-31 -> +16B (k 8-15).
    // af[g][mt][hl][4] : hl=0 -> hi (byte 0), hl=1 -> lo (byte 32).
    uint32_t af[2][2][2][4];
    {
        const uint32_t aoff =
            (uint32_t)(wr * 32 + (lane & 15)) * STRIDE_B + (lane >> 4) * 16;
        #pragma unroll
        for (int mt = 0; mt < 2; mt++) {
            #pragma unroll
            for (int hl = 0; hl < 2; hl++) {
                ldm_x4(af[0][mt][hl], sb + SM_A0 + aoff + mt * 16 * STRIDE_B + hl * 32);
                ldm_x4(af[1][mt][hl], sb + SM_A1 + aoff + mt * 16 * STRIDE_B + hl * 32);
            }
        }
    }

    // B fragment base: lanes 0-7 -> n rows (k0-7), 8-15 -> +16B (k8-15),
    // 16-23 -> n+8 rows, 24-31 -> n+8 rows +16B. One x4 covers an nt-pair.
    const uint32_t boff =
        (uint32_t)(wc * 64 + (lane & 7) + ((lane >> 4) << 3)) * STRIDE_B +
        ((lane >> 3) & 1) * 16;
    const uint32_t bAddr0 = sb + SM_B0 + boff;
    const uint32_t bAddr1 = sb + SM_B1 + boff;

    const int colb = col0 + wc * 64 + (lane & 3) * 2;
    const size_t rbase = (size_t)(row0 + wr * 32 + (lane >> 2));

    #pragma unroll
    for (int np = 0; np < 4; np++) {   // nt-pairs: 16 cols each
        const uint32_t bo = np * 16 * STRIDE_B;
        float accA[2][2][4] = {};      // [mt][nt][4], group 0
        float accB[2][2][4] = {};      // group 1

        // ---- group 0: load bh+bl, then 12 MMAs (4 chains x depth 3) ----
        {
            uint32_t bh[4], bl[4];
            ldm_x4(bh, bAddr0 + bo);
            ldm_x4(bl, bAddr0 + bo + 32);
            #pragma unroll
            for (int mt = 0; mt < 2; mt++)
                #pragma unroll
                for (int nt = 0; nt < 2; nt++) {
                    mma16816(accA[mt][nt], af[0][mt][0], bh[2*nt], bh[2*nt+1]);
                    mma16816(accA[mt][nt], af[0][mt][0], bl[2*nt], bl[2*nt+1]);
                    mma16816(accA[mt][nt], af[0][mt][1], bh[2*nt], bh[2*nt+1]);
                }
        }
        // ---- group 1 ----
        {
            uint32_t bh[4], bl[4];
            ldm_x4(bh, bAddr1 + bo);
            ldm_x4(bl, bAddr1 + bo + 32);
            #pragma unroll
            for (int mt = 0; mt < 2; mt++)
                #pragma unroll
                for (int nt = 0; nt < 2; nt++) {
                    mma16816(accB[mt][nt], af[1][mt][0], bh[2*nt], bh[2*nt+1]);
                    mma16816(accB[mt][nt], af[1][mt][0], bl[2*nt], bl[2*nt+1]);
                    mma16816(accB[mt][nt], af[1][mt][1], bh[2*nt], bh[2*nt+1]);
                }
        }

        // ---- epilogue: out = |D1 * D2| ----
        #pragma unroll
        for (int mt = 0; mt < 2; mt++) {
            #pragma unroll
            for (int nt = 0; nt < 2; nt++) {
                size_t rm = rbase + mt * 16;
                int cc = colb + np * 16 + nt * 8;
                float2 v;
                v.x = fabsf(accA[mt][nt][0] * accB[mt][nt][0]);
                v.y = fabsf(accA[mt][nt][1] * accB[mt][nt][1]);
                *(float2*)(out + rm * C + cc) = v;
                v.x = fabsf(accA[mt][nt][2] * accB[mt][nt][2]);
                v.y = fabsf(accA[mt][nt][3] * accB[mt][nt][3]);
                *(float2*)(out + (rm + 8) * C + cc) = v;
            }
        }
    }
}

extern "C" void kernel_launch(void* const* d_in, const int* in_sizes, int n_in,
                              void* d_out, int out_size) {
    const float* x = (const float*)d_in[0];
    const float* c = (const float*)d_in[1];
    float* out = (float*)d_out;

    int B = in_sizes[0] / 8;   // 8192
    int C = in_sizes[1] / 8;   // 2048
    if (B > BD) B = BD;
    if (C > CD) C = CD;

    int total = B + C;
    qk_pre<<<(total + 127) / 128, 128>>>(x, c, B, C);

    dim3 grid(C / 128, B / 128);
    qk_hmma<<<grid, 256>>>(out, C);
}